// round 13
// baseline (speedup 1.0000x reference)
#include <cuda_runtime.h>
#include <cuda_fp16.h>
#include <math.h>

#define NMAX 100000
#define EMAX 1600000
#define HID 128
#define NGRAPH 64
#define SCAN_BLK 512

// ---------------- device scratch ----------------
__device__ __half g_xh[(size_t)NMAX * HID];
__device__ __half g_wt[HID * HID];
__device__ __half g_yh[(size_t)NMAX * HID];    // fp16 xt, scaled by dinv in k_yscale
__device__ float g_dinv[NMAX];
__device__ int   g_deg[NMAX];                  // zeroed by k_gatesx of PREVIOUS run (.bss on first)
__device__ int   g_start[NMAX + 1];
__device__ int   g_cursor[NMAX];
__device__ int   g_csr_src[EMAX];
__device__ int   g_part[(NMAX + SCAN_BLK - 1) / SCAN_BLK];
__device__ float g_gsum[NGRAPH * HID];         // zeroed by k_gatesx after read
__device__ float g_gcnt[NGRAPH];
__device__ float g_gatesX[NGRAPH * 4 * HID];
__device__ __half g_whh_h[4 * HID * HID];

// ---------------- fp16 conversions ----------------
__global__ void k_cvtx(const float* __restrict__ x, int total8) {
    int i = blockIdx.x * blockDim.x + threadIdx.x;
    if (i < total8) {
        float4 v0 = __ldg((const float4*)x + (size_t)i * 2);
        float4 v1 = __ldg((const float4*)x + (size_t)i * 2 + 1);
        __half2 h0 = __floats2half2_rn(v0.x, v0.y);
        __half2 h1 = __floats2half2_rn(v0.z, v0.w);
        __half2 h2 = __floats2half2_rn(v1.x, v1.y);
        __half2 h3 = __floats2half2_rn(v1.z, v1.w);
        uint4 p;
        p.x = *(unsigned*)&h0; p.y = *(unsigned*)&h1;
        p.z = *(unsigned*)&h2; p.w = *(unsigned*)&h3;
        *(uint4*)(g_xh + (size_t)i * 8) = p;
    }
}

__global__ void k_cvtw(const float* __restrict__ W, const float* __restrict__ w_hh) {
    int i = blockIdx.x * blockDim.x + threadIdx.x;
    if (i < HID * HID) {
        int n = i >> 7, k = i & 127;
        g_wt[n * HID + k] = __float2half(__ldg(&W[k * HID + n]));
    }
    if (i < 4 * HID * HID) g_whh_h[i] = __float2half(__ldg(&w_hh[i]));
}

// ---------------- degree histogram over col ----------------
__global__ void k_deg(const int* __restrict__ ei, int E) {
    int e = blockIdx.x * blockDim.x + threadIdx.x;
    if (e < E) atomicAdd(&g_deg[__ldg(&ei[(size_t)E + e])], 1);
}

// ---------------- scan pass 1: block sums + dinv ----------------
__global__ __launch_bounds__(SCAN_BLK) void k_scan1(int N) {
    int i = blockIdx.x * SCAN_BLK + threadIdx.x;
    int v = (i < N) ? g_deg[i] : 0;
    if (i < N) g_dinv[i] = rsqrtf((float)v + 1.0f);
    int s = v;
    for (int o = 16; o > 0; o >>= 1) s += __shfl_down_sync(0xffffffffu, s, o);
    __shared__ int ws[16];
    int wid = threadIdx.x >> 5, lane = threadIdx.x & 31;
    if (lane == 0) ws[wid] = s;
    __syncthreads();
    if (threadIdx.x < 16) {
        int t = ws[threadIdx.x];
        for (int o = 8; o > 0; o >>= 1) t += __shfl_down_sync(0xffffu, t, o);
        if (threadIdx.x == 0) g_part[blockIdx.x] = t;
    }
}

// ---------------- scan 2+3 merged ----------------
__global__ __launch_bounds__(SCAN_BLK) void k_scan23(int N, int NB) {
    int bid = blockIdx.x;
    int i = bid * SCAN_BLK + threadIdx.x;
    int v = (i < N) ? g_deg[i] : 0;
    int lane = threadIdx.x & 31, wid = threadIdx.x >> 5;
    int x = v;
    for (int o = 1; o < 32; o <<= 1) {
        int t = __shfl_up_sync(0xffffffffu, x, o);
        if (lane >= o) x += t;
    }
    __shared__ int ws[16], pws[16], sbase;
    if (lane == 31) ws[wid] = x;
    int pv = ((int)threadIdx.x < bid) ? g_part[threadIdx.x] : 0;
    for (int o = 16; o > 0; o >>= 1) pv += __shfl_down_sync(0xffffffffu, pv, o);
    if (lane == 0) pws[wid] = pv;
    __syncthreads();
    if (wid == 0 && lane < 16) {
        int t = ws[lane];
        for (int o = 1; o < 16; o <<= 1) {
            int u = __shfl_up_sync(0xffffu, t, o);
            if (lane >= o) t += u;
        }
        ws[lane] = t;
    }
    if (wid == 1 && lane < 16) {
        int t = pws[lane];
        for (int o = 8; o > 0; o >>= 1) t += __shfl_down_sync(0xffffu, t, o);
        if (lane == 0) sbase = t;
    }
    __syncthreads();
    int base = sbase + (wid > 0 ? ws[wid - 1] : 0);
    int excl = base + (x - v);
    if (i < N) { g_start[i] = excl; g_cursor[i] = excl; }
    if (i == N - 1) g_start[N] = excl + v;
}

// ---------------- CSR fill: 4 edges/thread, int4 loads ----------------
__global__ void k_fill(const int* __restrict__ ei, int E) {
    int q = blockIdx.x * blockDim.x + threadIdx.x;
    if (q * 4 < E) {
        int4 rows = __ldg((const int4*)(ei) + q);
        int4 cols = __ldg((const int4*)(ei + E) + q);
        int s0 = atomicAdd(&g_cursor[cols.x], 1); g_csr_src[s0] = rows.x;
        int s1 = atomicAdd(&g_cursor[cols.y], 1); g_csr_src[s1] = rows.y;
        int s2 = atomicAdd(&g_cursor[cols.z], 1); g_csr_src[s2] = rows.z;
        int s3 = atomicAdd(&g_cursor[cols.w], 1); g_csr_src[s3] = rows.w;
    }
}

// ---------------- tensor-core GEMM: yh[n] = fp16( x[n] @ W )  (4th submission -> ncu) ----------------
__global__ __launch_bounds__(256) void k_gemm_tc(int M) {
    __shared__ __half xs[128][72];
    __shared__ __half ws[128][72];
    int tid = threadIdx.x;
    int warp = tid >> 5, lane = tid & 31;
    int wm = (warp & 3) * 32;
    int wn = (warp >> 2) * 64;
    int g = lane >> 2, tig = lane & 3;
    int m0 = blockIdx.x * 128;

    float acc[2][8][4];
#pragma unroll
    for (int mt = 0; mt < 2; mt++)
#pragma unroll
        for (int nt = 0; nt < 8; nt++)
#pragma unroll
            for (int q = 0; q < 4; q++) acc[mt][nt][q] = 0.f;

    for (int kc = 0; kc < 2; kc++) {
#pragma unroll
        for (int i = 0; i < 4; i++) {
            int idx = i * 256 + tid;
            int r = idx >> 3, q = idx & 7;
            int grow = m0 + r;
            uint4 v = make_uint4(0u, 0u, 0u, 0u);
            if (grow < M)
                v = *(const uint4*)(g_xh + (size_t)grow * HID + kc * 64 + q * 8);
            *(uint4*)(&xs[r][q * 8]) = v;
            uint4 w = *(const uint4*)(g_wt + r * HID + kc * 64 + q * 8);
            *(uint4*)(&ws[r][q * 8]) = w;
        }
        __syncthreads();
#pragma unroll
        for (int ks = 0; ks < 4; ks++) {
            int k0 = ks * 16;
            unsigned a[2][4];
#pragma unroll
            for (int mt = 0; mt < 2; mt++) {
                int row = wm + mt * 16 + g;
                a[mt][0] = *(const unsigned*)(&xs[row][k0 + tig * 2]);
                a[mt][1] = *(const unsigned*)(&xs[row + 8][k0 + tig * 2]);
                a[mt][2] = *(const unsigned*)(&xs[row][k0 + tig * 2 + 8]);
                a[mt][3] = *(const unsigned*)(&xs[row + 8][k0 + tig * 2 + 8]);
            }
#pragma unroll
            for (int nt = 0; nt < 8; nt++) {
                int n = wn + nt * 8 + g;
                unsigned b0 = *(const unsigned*)(&ws[n][k0 + tig * 2]);
                unsigned b1 = *(const unsigned*)(&ws[n][k0 + tig * 2 + 8]);
#pragma unroll
                for (int mt = 0; mt < 2; mt++) {
                    float* c = acc[mt][nt];
                    asm volatile(
                        "mma.sync.aligned.m16n8k16.row.col.f32.f16.f16.f32 "
                        "{%0,%1,%2,%3}, {%4,%5,%6,%7}, {%8,%9}, {%0,%1,%2,%3};"
                        : "+f"(c[0]), "+f"(c[1]), "+f"(c[2]), "+f"(c[3])
                        : "r"(a[mt][0]), "r"(a[mt][1]), "r"(a[mt][2]), "r"(a[mt][3]),
                          "r"(b0), "r"(b1));
                }
            }
        }
        __syncthreads();
    }

#pragma unroll
    for (int mt = 0; mt < 2; mt++) {
        int row = m0 + wm + mt * 16 + g;
#pragma unroll
        for (int nt = 0; nt < 8; nt++) {
            int col = wn + nt * 8 + tig * 2;
            float* c = acc[mt][nt];
            if (row < M) {
                __half2 h = __floats2half2_rn(c[0], c[1]);
                *(__half2*)(g_yh + (size_t)row * HID + col) = h;
            }
            if (row + 8 < M) {
                __half2 h = __floats2half2_rn(c[2], c[3]);
                *(__half2*)(g_yh + (size_t)(row + 8) * HID + col) = h;
            }
        }
    }
}

// ---------------- yscale: g_yh[n] *= dinv[n] ----------------
__global__ void k_yscale(int total16) {
    int i = blockIdx.x * blockDim.x + threadIdx.x;
    if (i < total16) {
        int n = i >> 4;
        uint4 v = *(const uint4*)(g_yh + (size_t)i * 8);
        __half2 dh = __float2half2_rn(g_dinv[n]);
        __half2* p = (__half2*)&v;
        p[0] = __hmul2(p[0], dh);
        p[1] = __hmul2(p[1], dh);
        p[2] = __hmul2(p[2], dh);
        p[3] = __hmul2(p[3], dh);
        *(uint4*)(g_yh + (size_t)i * 8) = v;
    }
}

// ---------------- fused gather-aggregate + relu + mean-pool ----------------
__device__ __forceinline__ void pool_flush(int g, float4 run, float crun, int lane) {
    float* dst = g_gsum + g * HID + lane * 4;
    asm volatile("red.global.add.v4.f32 [%0], {%1,%2,%3,%4};"
                 :: "l"(dst), "f"(run.x), "f"(run.y), "f"(run.z), "f"(run.w) : "memory");
    if (lane == 0) atomicAdd(&g_gcnt[g], crun);
}

__device__ __forceinline__ void add_row(float4& acc, uint2 r) {
    float2 lo = __half22float2(*(const __half2*)&r.x);
    float2 hi = __half22float2(*(const __half2*)&r.y);
    acc.x += lo.x; acc.y += lo.y; acc.z += hi.x; acc.w += hi.y;
}

__global__ __launch_bounds__(256) void k_agg(const int* __restrict__ batch,
                                             const float* __restrict__ b_gcn, int N) {
    int lane = threadIdx.x & 31, wid = threadIdx.x >> 5;
    int s0 = blockIdx.x * 32;
    int e0 = min(s0 + 32, N);
    int n0 = s0 + wid;
    if (n0 >= e0) return;

    float4 bb = __ldg((const float4*)(b_gcn + lane * 4));
    int curg = __ldg(&batch[n0]);
    float4 run = make_float4(0.f, 0.f, 0.f, 0.f);
    float crun = 0.f;

    for (int n = n0; n < e0; n += 8) {
        int gg = __ldg(&batch[n]);
        if (gg != curg) {
            pool_flush(curg, run, crun, lane);
            run = make_float4(0.f, 0.f, 0.f, 0.f);
            crun = 0.f;
            curg = gg;
        }
        int st = __ldg(&g_start[n]);
        int en = __ldg(&g_start[n + 1]);
        float dvn = __ldg(&g_dinv[n]);
        float4 acc = make_float4(0.f, 0.f, 0.f, 0.f);
        add_row(acc, __ldg((const uint2*)(g_yh + (size_t)n * HID) + lane));  // self loop
        for (int base = st; base < en; base += 32) {
            int cnt = min(32, en - base);
            int id = (lane < cnt) ? __ldg(&g_csr_src[base + lane]) : 0;
            int j = 0;
            for (; j + 4 <= cnt; j += 4) {
                int a0 = __shfl_sync(0xffffffffu, id, j);
                int a1 = __shfl_sync(0xffffffffu, id, j + 1);
                int a2 = __shfl_sync(0xffffffffu, id, j + 2);
                int a3 = __shfl_sync(0xffffffffu, id, j + 3);
                uint2 r0 = __ldg((const uint2*)(g_yh + (size_t)a0 * HID) + lane);
                uint2 r1 = __ldg((const uint2*)(g_yh + (size_t)a1 * HID) + lane);
                uint2 r2 = __ldg((const uint2*)(g_yh + (size_t)a2 * HID) + lane);
                uint2 r3 = __ldg((const uint2*)(g_yh + (size_t)a3 * HID) + lane);
                add_row(acc, r0);
                add_row(acc, r1);
                add_row(acc, r2);
                add_row(acc, r3);
            }
            for (; j < cnt; j++) {
                int a0 = __shfl_sync(0xffffffffu, id, j);
                add_row(acc, __ldg((const uint2*)(g_yh + (size_t)a0 * HID) + lane));
            }
        }
        run.x += fmaxf(fmaf(acc.x, dvn, bb.x), 0.f);
        run.y += fmaxf(fmaf(acc.y, dvn, bb.y), 0.f);
        run.z += fmaxf(fmaf(acc.z, dvn, bb.z), 0.f);
        run.w += fmaxf(fmaf(acc.w, dvn, bb.w), 0.f);
        crun += 1.f;
    }
    pool_flush(curg, run, crun, lane);
}

// ---------------- input-side LSTM gates + state re-zero for next replay ----------------
__global__ __launch_bounds__(512) void k_gatesx(const float* __restrict__ w_ih,
                                                const float* __restrict__ b_ih,
                                                const float* __restrict__ b_hh, int N) {
    __shared__ float p[HID];
    int t = blockIdx.x;
    if (threadIdx.x < HID) {
        float c = fmaxf(g_gcnt[t], 1.f);
        p[threadIdx.x] = g_gsum[t * HID + threadIdx.x] / c;
    }
    __syncthreads();
    int gg = threadIdx.x;
    const float4* wr = (const float4*)(w_ih + (size_t)gg * HID);
    float acc = __ldg(&b_ih[gg]) + __ldg(&b_hh[gg]);
#pragma unroll
    for (int j = 0; j < 32; j++) {
        float4 w = __ldg(wr + j);
        acc += w.x * p[j * 4] + w.y * p[j * 4 + 1] + w.z * p[j * 4 + 2] + w.w * p[j * 4 + 3];
    }
    g_gatesX[t * 512 + gg] = acc;
    // re-zero accumulators for the NEXT kernel_launch invocation (post-read)
    if (threadIdx.x < HID) g_gsum[t * HID + threadIdx.x] = 0.f;
    if (threadIdx.x == 0) g_gcnt[t] = 0.f;
    for (int i = t * 512 + threadIdx.x; i < N; i += NGRAPH * 512) g_deg[i] = 0;
}

// ---------------- recurrent LSTM (fp16 weights, 4-way acc) + fused FC ----------------
// IDEMPOTENT: launched twice this round; dur delta vs R12 reads out T_lstm.
__global__ __launch_bounds__(512) void k_lstm(const float* __restrict__ W_fc,
                                              const float* __restrict__ b_fc,
                                              float* __restrict__ out) {
    __shared__ float sh[HID];
    __shared__ float sg[4 * HID];
    int tid = threadIdx.x;
    float c = 0.f;
    if (tid < HID) sh[tid] = 0.f;
    __syncthreads();
    const uint4* wr = (const uint4*)(g_whh_h + (size_t)tid * HID);
    for (int t = 0; t < NGRAPH; t++) {
        float a0 = g_gatesX[t * 512 + tid], a1 = 0.f, a2 = 0.f, a3 = 0.f;
#pragma unroll
        for (int j = 0; j < 16; j += 4) {
#pragma unroll
            for (int u = 0; u < 4; u++) {
                uint4 w = __ldg(&wr[j + u]);
                float2 p0 = __half22float2(*(const __half2*)&w.x);
                float2 p1 = __half22float2(*(const __half2*)&w.y);
                float2 p2 = __half22float2(*(const __half2*)&w.z);
                float2 p3 = __half22float2(*(const __half2*)&w.w);
                const float* h = &sh[(j + u) * 8];
                a0 = fmaf(p0.x, h[0], a0); a1 = fmaf(p0.y, h[1], a1);
                a2 = fmaf(p1.x, h[2], a2); a3 = fmaf(p1.y, h[3], a3);
                a0 = fmaf(p2.x, h[4], a0); a1 = fmaf(p2.y, h[5], a1);
                a2 = fmaf(p3.x, h[6], a2); a3 = fmaf(p3.y, h[7], a3);
            }
        }
        sg[tid] = (a0 + a1) + (a2 + a3);
        __syncthreads();
        if (tid < HID) {
            float iv = 1.f / (1.f + __expf(-sg[tid]));
            float fv = 1.f / (1.f + __expf(-sg[HID + tid]));
            float gv = tanhf(sg[2 * HID + tid]);
            float ov = 1.f / (1.f + __expf(-sg[3 * HID + tid]));
            c = fv * c + iv * gv;
            sh[tid] = ov * tanhf(c);
        }
        __syncthreads();
        if (tid < 320) {
            int k = tid >> 5, lane = tid & 31;
            const float4* wf = (const float4*)(W_fc + (size_t)k * HID);
            float4 w = __ldg(&wf[lane]);
            float4 h4 = *(const float4*)&sh[lane * 4];
            float p = w.x * h4.x + w.y * h4.y + w.z * h4.z + w.w * h4.w;
            for (int o = 16; o > 0; o >>= 1) p += __shfl_down_sync(0xffffffffu, p, o);
            if (lane == 0) out[t * 10 + k] = p + __ldg(&b_fc[k]);
        }
    }
}

// ---------------- launch ----------------
extern "C" void kernel_launch(void* const* d_in, const int* in_sizes, int n_in,
                              void* d_out, int out_size) {
    const float* x      = (const float*)d_in[0];
    const int*   ei     = (const int*)d_in[1];
    const int*   batch  = (const int*)d_in[2];
    const float* W_gcn  = (const float*)d_in[3];
    const float* b_gcn  = (const float*)d_in[4];
    const float* w_ih   = (const float*)d_in[5];
    const float* w_hh   = (const float*)d_in[6];
    const float* b_ih   = (const float*)d_in[7];
    const float* b_hh   = (const float*)d_in[8];
    const float* W_fc   = (const float*)d_in[9];
    const float* b_fc   = (const float*)d_in[10];
    float* out = (float*)d_out;

    int N = in_sizes[2];       // 100000 nodes
    int E = in_sizes[1] / 2;   // 1600000 edges
    int NB = (N + SCAN_BLK - 1) / SCAN_BLK;

    static cudaStream_t s2 = nullptr;
    static cudaEvent_t ev0 = nullptr, evS1 = nullptr, evB = nullptr;
    if (s2 == nullptr) {
        cudaStreamCreate(&s2);
        cudaEventCreateWithFlags(&ev0, cudaEventDisableTiming);
        cudaEventCreateWithFlags(&evS1, cudaEventDisableTiming);
        cudaEventCreateWithFlags(&evB, cudaEventDisableTiming);
    }

    cudaEventRecord(ev0, 0);
    cudaStreamWaitEvent(s2, ev0, 0);

    // Submission order chosen so the 4th launch (ncu slot) is k_gemm_tc.
    k_deg<<<(E + 255) / 256, 256>>>(ei, E);                                 // 1 (main)
    k_cvtx<<<(N * HID / 8 + 255) / 256, 256, 0, s2>>>(x, N * HID / 8);      // 2 (s2)
    k_cvtw<<<(4 * HID * HID + 255) / 256, 256, 0, s2>>>(W_gcn, w_hh);       // 3 (s2)
    k_gemm_tc<<<(N + 127) / 128, 256, 0, s2>>>(N);                          // 4 (s2) <- ncu

    k_scan1<<<NB, SCAN_BLK>>>(N);                                           // 5 (main)
    cudaEventRecord(evS1, 0);
    cudaStreamWaitEvent(s2, evS1, 0);
    k_yscale<<<(N * 16 + 255) / 256, 256, 0, s2>>>(N * 16);                 // 6 (s2)
    cudaEventRecord(evB, s2);

    k_scan23<<<NB, SCAN_BLK>>>(N, NB);                                      // 7 (main)
    k_fill<<<(E / 4 + 255) / 256, 256>>>(ei, E);                            // 8 (main)

    cudaStreamWaitEvent(0, evB, 0);
    k_agg<<<(N + 31) / 32, 256>>>(batch, b_gcn, N);                         // 9
    k_gatesx<<<NGRAPH, 512>>>(w_ih, b_ih, b_hh, N);                         // 10
    k_lstm<<<1, 512>>>(W_fc, b_fc, out);                                    // 11
    k_lstm<<<1, 512>>>(W_fc, b_fc, out);                                    // 12 (probe: dur delta = T_lstm)
}

// round 14
// speedup vs baseline: 2.4131x; 2.4131x over previous
#include <cuda_runtime.h>
#include <cuda_fp16.h>
#include <math.h>

#define NMAX 100000
#define EMAX 1600000
#define HID 128
#define NGRAPH 64
#define SCAN_BLK 512

// ---------------- device scratch ----------------
__device__ __half g_xh[(size_t)NMAX * HID];
__device__ __half g_wt[HID * HID];
__device__ __half g_yh[(size_t)NMAX * HID];    // fp16 xt, scaled by dinv in k_yscale
__device__ float g_dinv[NMAX];
__device__ int   g_deg[NMAX];                  // zeroed by k_gatesx of PREVIOUS run (.bss on first)
__device__ int   g_start[NMAX + 1];
__device__ int   g_cursor[NMAX];
__device__ int   g_csr_src[EMAX];
__device__ int   g_part[(NMAX + SCAN_BLK - 1) / SCAN_BLK];
__device__ float g_gsum[NGRAPH * HID];         // zeroed by k_gatesx after read
__device__ float g_gcnt[NGRAPH];
__device__ float g_gatesX[NGRAPH * 4 * HID];
__device__ __half g_whh_h[4 * HID * HID];

// ---------------- fp16 conversions ----------------
__global__ void k_cvtx(const float* __restrict__ x, int total8) {
    int i = blockIdx.x * blockDim.x + threadIdx.x;
    if (i < total8) {
        float4 v0 = __ldg((const float4*)x + (size_t)i * 2);
        float4 v1 = __ldg((const float4*)x + (size_t)i * 2 + 1);
        __half2 h0 = __floats2half2_rn(v0.x, v0.y);
        __half2 h1 = __floats2half2_rn(v0.z, v0.w);
        __half2 h2 = __floats2half2_rn(v1.x, v1.y);
        __half2 h3 = __floats2half2_rn(v1.z, v1.w);
        uint4 p;
        p.x = *(unsigned*)&h0; p.y = *(unsigned*)&h1;
        p.z = *(unsigned*)&h2; p.w = *(unsigned*)&h3;
        *(uint4*)(g_xh + (size_t)i * 8) = p;
    }
}

__global__ void k_cvtw(const float* __restrict__ W, const float* __restrict__ w_hh) {
    int i = blockIdx.x * blockDim.x + threadIdx.x;
    if (i < HID * HID) {
        int n = i >> 7, k = i & 127;
        g_wt[n * HID + k] = __float2half(__ldg(&W[k * HID + n]));
    }
    if (i < 4 * HID * HID) g_whh_h[i] = __float2half(__ldg(&w_hh[i]));
}

// ---------------- degree histogram over col ----------------
__global__ void k_deg(const int* __restrict__ ei, int E) {
    int e = blockIdx.x * blockDim.x + threadIdx.x;
    if (e < E) atomicAdd(&g_deg[__ldg(&ei[(size_t)E + e])], 1);
}

// ---------------- scan pass 1: block sums + dinv (4th submission -> ncu) ----------------
__global__ __launch_bounds__(SCAN_BLK) void k_scan1(int N) {
    int i = blockIdx.x * SCAN_BLK + threadIdx.x;
    int v = (i < N) ? g_deg[i] : 0;
    if (i < N) g_dinv[i] = rsqrtf((float)v + 1.0f);
    int s = v;
    for (int o = 16; o > 0; o >>= 1) s += __shfl_down_sync(0xffffffffu, s, o);
    __shared__ int ws[16];
    int wid = threadIdx.x >> 5, lane = threadIdx.x & 31;
    if (lane == 0) ws[wid] = s;
    __syncthreads();
    if (threadIdx.x < 16) {
        int t = ws[threadIdx.x];
        for (int o = 8; o > 0; o >>= 1) t += __shfl_down_sync(0xffffu, t, o);
        if (threadIdx.x == 0) g_part[blockIdx.x] = t;
    }
}

// ---------------- scan 2+3 merged ----------------
__global__ __launch_bounds__(SCAN_BLK) void k_scan23(int N, int NB) {
    int bid = blockIdx.x;
    int i = bid * SCAN_BLK + threadIdx.x;
    int v = (i < N) ? g_deg[i] : 0;
    int lane = threadIdx.x & 31, wid = threadIdx.x >> 5;
    int x = v;
    for (int o = 1; o < 32; o <<= 1) {
        int t = __shfl_up_sync(0xffffffffu, x, o);
        if (lane >= o) x += t;
    }
    __shared__ int ws[16], pws[16], sbase;
    if (lane == 31) ws[wid] = x;
    int pv = ((int)threadIdx.x < bid) ? g_part[threadIdx.x] : 0;
    for (int o = 16; o > 0; o >>= 1) pv += __shfl_down_sync(0xffffffffu, pv, o);
    if (lane == 0) pws[wid] = pv;
    __syncthreads();
    if (wid == 0 && lane < 16) {
        int t = ws[lane];
        for (int o = 1; o < 16; o <<= 1) {
            int u = __shfl_up_sync(0xffffu, t, o);
            if (lane >= o) t += u;
        }
        ws[lane] = t;
    }
    if (wid == 1 && lane < 16) {
        int t = pws[lane];
        for (int o = 8; o > 0; o >>= 1) t += __shfl_down_sync(0xffffu, t, o);
        if (lane == 0) sbase = t;
    }
    __syncthreads();
    int base = sbase + (wid > 0 ? ws[wid - 1] : 0);
    int excl = base + (x - v);
    if (i < N) { g_start[i] = excl; g_cursor[i] = excl; }
    if (i == N - 1) g_start[N] = excl + v;
}

// ---------------- CSR fill: 4 edges/thread, int4 loads ----------------
__global__ void k_fill(const int* __restrict__ ei, int E) {
    int q = blockIdx.x * blockDim.x + threadIdx.x;
    if (q * 4 < E) {
        int4 rows = __ldg((const int4*)(ei) + q);
        int4 cols = __ldg((const int4*)(ei + E) + q);
        int s0 = atomicAdd(&g_cursor[cols.x], 1); g_csr_src[s0] = rows.x;
        int s1 = atomicAdd(&g_cursor[cols.y], 1); g_csr_src[s1] = rows.y;
        int s2 = atomicAdd(&g_cursor[cols.z], 1); g_csr_src[s2] = rows.z;
        int s3 = atomicAdd(&g_cursor[cols.w], 1); g_csr_src[s3] = rows.w;
    }
}

// ---------------- tensor-core GEMM: yh[n] = fp16( x[n] @ W ) ----------------
__global__ __launch_bounds__(256) void k_gemm_tc(int M) {
    __shared__ __half xs[128][72];
    __shared__ __half ws[128][72];
    int tid = threadIdx.x;
    int warp = tid >> 5, lane = tid & 31;
    int wm = (warp & 3) * 32;
    int wn = (warp >> 2) * 64;
    int g = lane >> 2, tig = lane & 3;
    int m0 = blockIdx.x * 128;

    float acc[2][8][4];
#pragma unroll
    for (int mt = 0; mt < 2; mt++)
#pragma unroll
        for (int nt = 0; nt < 8; nt++)
#pragma unroll
            for (int q = 0; q < 4; q++) acc[mt][nt][q] = 0.f;

    for (int kc = 0; kc < 2; kc++) {
#pragma unroll
        for (int i = 0; i < 4; i++) {
            int idx = i * 256 + tid;
            int r = idx >> 3, q = idx & 7;
            int grow = m0 + r;
            uint4 v = make_uint4(0u, 0u, 0u, 0u);
            if (grow < M)
                v = *(const uint4*)(g_xh + (size_t)grow * HID + kc * 64 + q * 8);
            *(uint4*)(&xs[r][q * 8]) = v;
            uint4 w = *(const uint4*)(g_wt + r * HID + kc * 64 + q * 8);
            *(uint4*)(&ws[r][q * 8]) = w;
        }
        __syncthreads();
#pragma unroll
        for (int ks = 0; ks < 4; ks++) {
            int k0 = ks * 16;
            unsigned a[2][4];
#pragma unroll
            for (int mt = 0; mt < 2; mt++) {
                int row = wm + mt * 16 + g;
                a[mt][0] = *(const unsigned*)(&xs[row][k0 + tig * 2]);
                a[mt][1] = *(const unsigned*)(&xs[row + 8][k0 + tig * 2]);
                a[mt][2] = *(const unsigned*)(&xs[row][k0 + tig * 2 + 8]);
                a[mt][3] = *(const unsigned*)(&xs[row + 8][k0 + tig * 2 + 8]);
            }
#pragma unroll
            for (int nt = 0; nt < 8; nt++) {
                int n = wn + nt * 8 + g;
                unsigned b0 = *(const unsigned*)(&ws[n][k0 + tig * 2]);
                unsigned b1 = *(const unsigned*)(&ws[n][k0 + tig * 2 + 8]);
#pragma unroll
                for (int mt = 0; mt < 2; mt++) {
                    float* c = acc[mt][nt];
                    asm volatile(
                        "mma.sync.aligned.m16n8k16.row.col.f32.f16.f16.f32 "
                        "{%0,%1,%2,%3}, {%4,%5,%6,%7}, {%8,%9}, {%0,%1,%2,%3};"
                        : "+f"(c[0]), "+f"(c[1]), "+f"(c[2]), "+f"(c[3])
                        : "r"(a[mt][0]), "r"(a[mt][1]), "r"(a[mt][2]), "r"(a[mt][3]),
                          "r"(b0), "r"(b1));
                }
            }
        }
        __syncthreads();
    }

#pragma unroll
    for (int mt = 0; mt < 2; mt++) {
        int row = m0 + wm + mt * 16 + g;
#pragma unroll
        for (int nt = 0; nt < 8; nt++) {
            int col = wn + nt * 8 + tig * 2;
            float* c = acc[mt][nt];
            if (row < M) {
                __half2 h = __floats2half2_rn(c[0], c[1]);
                *(__half2*)(g_yh + (size_t)row * HID + col) = h;
            }
            if (row + 8 < M) {
                __half2 h = __floats2half2_rn(c[2], c[3]);
                *(__half2*)(g_yh + (size_t)(row + 8) * HID + col) = h;
            }
        }
    }
}

// ---------------- yscale: g_yh[n] *= dinv[n] ----------------
__global__ void k_yscale(int total16) {
    int i = blockIdx.x * blockDim.x + threadIdx.x;
    if (i < total16) {
        int n = i >> 4;
        uint4 v = *(const uint4*)(g_yh + (size_t)i * 8);
        __half2 dh = __float2half2_rn(g_dinv[n]);
        __half2* p = (__half2*)&v;
        p[0] = __hmul2(p[0], dh);
        p[1] = __hmul2(p[1], dh);
        p[2] = __hmul2(p[2], dh);
        p[3] = __hmul2(p[3], dh);
        *(uint4*)(g_yh + (size_t)i * 8) = v;
    }
}

// ---------------- fused gather-aggregate + relu + mean-pool ----------------
// NOTE: launched TWICE this round (probe). Doubling is mean-preserving:
// gsum and gcnt both double; gatesx computes gsum/gcnt.
__device__ __forceinline__ void pool_flush(int g, float4 run, float crun, int lane) {
    float* dst = g_gsum + g * HID + lane * 4;
    asm volatile("red.global.add.v4.f32 [%0], {%1,%2,%3,%4};"
                 :: "l"(dst), "f"(run.x), "f"(run.y), "f"(run.z), "f"(run.w) : "memory");
    if (lane == 0) atomicAdd(&g_gcnt[g], crun);
}

__device__ __forceinline__ void add_row(float4& acc, uint2 r) {
    float2 lo = __half22float2(*(const __half2*)&r.x);
    float2 hi = __half22float2(*(const __half2*)&r.y);
    acc.x += lo.x; acc.y += lo.y; acc.z += hi.x; acc.w += hi.y;
}

__global__ __launch_bounds__(256) void k_agg(const int* __restrict__ batch,
                                             const float* __restrict__ b_gcn, int N) {
    int lane = threadIdx.x & 31, wid = threadIdx.x >> 5;
    int s0 = blockIdx.x * 32;
    int e0 = min(s0 + 32, N);
    int n0 = s0 + wid;
    if (n0 >= e0) return;

    float4 bb = __ldg((const float4*)(b_gcn + lane * 4));
    int curg = __ldg(&batch[n0]);
    float4 run = make_float4(0.f, 0.f, 0.f, 0.f);
    float crun = 0.f;

    for (int n = n0; n < e0; n += 8) {
        int gg = __ldg(&batch[n]);
        if (gg != curg) {
            pool_flush(curg, run, crun, lane);
            run = make_float4(0.f, 0.f, 0.f, 0.f);
            crun = 0.f;
            curg = gg;
        }
        int st = __ldg(&g_start[n]);
        int en = __ldg(&g_start[n + 1]);
        float dvn = __ldg(&g_dinv[n]);
        float4 acc = make_float4(0.f, 0.f, 0.f, 0.f);
        add_row(acc, __ldg((const uint2*)(g_yh + (size_t)n * HID) + lane));  // self loop
        for (int base = st; base < en; base += 32) {
            int cnt = min(32, en - base);
            int id = (lane < cnt) ? __ldg(&g_csr_src[base + lane]) : 0;
            int j = 0;
            for (; j + 4 <= cnt; j += 4) {
                int a0 = __shfl_sync(0xffffffffu, id, j);
                int a1 = __shfl_sync(0xffffffffu, id, j + 1);
                int a2 = __shfl_sync(0xffffffffu, id, j + 2);
                int a3 = __shfl_sync(0xffffffffu, id, j + 3);
                uint2 r0 = __ldg((const uint2*)(g_yh + (size_t)a0 * HID) + lane);
                uint2 r1 = __ldg((const uint2*)(g_yh + (size_t)a1 * HID) + lane);
                uint2 r2 = __ldg((const uint2*)(g_yh + (size_t)a2 * HID) + lane);
                uint2 r3 = __ldg((const uint2*)(g_yh + (size_t)a3 * HID) + lane);
                add_row(acc, r0);
                add_row(acc, r1);
                add_row(acc, r2);
                add_row(acc, r3);
            }
            for (; j < cnt; j++) {
                int a0 = __shfl_sync(0xffffffffu, id, j);
                add_row(acc, __ldg((const uint2*)(g_yh + (size_t)a0 * HID) + lane));
            }
        }
        run.x += fmaxf(fmaf(acc.x, dvn, bb.x), 0.f);
        run.y += fmaxf(fmaf(acc.y, dvn, bb.y), 0.f);
        run.z += fmaxf(fmaf(acc.z, dvn, bb.z), 0.f);
        run.w += fmaxf(fmaf(acc.w, dvn, bb.w), 0.f);
        crun += 1.f;
    }
    pool_flush(curg, run, crun, lane);
}

// ---------------- input-side LSTM gates + state re-zero for next replay ----------------
__global__ __launch_bounds__(512) void k_gatesx(const float* __restrict__ w_ih,
                                                const float* __restrict__ b_ih,
                                                const float* __restrict__ b_hh, int N) {
    __shared__ float p[HID];
    int t = blockIdx.x;
    if (threadIdx.x < HID) {
        float c = fmaxf(g_gcnt[t], 1.f);
        p[threadIdx.x] = g_gsum[t * HID + threadIdx.x] / c;
    }
    __syncthreads();
    int gg = threadIdx.x;
    const float4* wr = (const float4*)(w_ih + (size_t)gg * HID);
    float acc = __ldg(&b_ih[gg]) + __ldg(&b_hh[gg]);
#pragma unroll
    for (int j = 0; j < 32; j++) {
        float4 w = __ldg(wr + j);
        acc += w.x * p[j * 4] + w.y * p[j * 4 + 1] + w.z * p[j * 4 + 2] + w.w * p[j * 4 + 3];
    }
    g_gatesX[t * 512 + gg] = acc;
    // re-zero accumulators for the NEXT kernel_launch invocation (post-read)
    if (threadIdx.x < HID) g_gsum[t * HID + threadIdx.x] = 0.f;
    if (threadIdx.x == 0) g_gcnt[t] = 0.f;
    for (int i = t * 512 + threadIdx.x; i < N; i += NGRAPH * 512) g_deg[i] = 0;
}

// ---------------- recurrent LSTM: REGISTER-RESIDENT fp16 weights + fused FC ----------------
// R13 showed the old per-step weight loads were 8192 L1 wavefronts/step
// (lane stride 256B -> nL=32 per warp LDG). Weights now live in 64 regs/thread,
// loaded once; per-step traffic is broadcast-LDS of h only.
__global__ __launch_bounds__(512) void k_lstm(const float* __restrict__ W_fc,
                                              const float* __restrict__ b_fc,
                                              float* __restrict__ out) {
    __shared__ float sh[HID];
    __shared__ float sg[4 * HID];
    int tid = threadIdx.x;

    // one-time weight load: row tid of w_hh into registers (16 x uint4 = 64 regs)
    uint4 wreg[16];
    {
        const uint4* wr = (const uint4*)(g_whh_h + (size_t)tid * HID);
#pragma unroll
        for (int j = 0; j < 16; j++) wreg[j] = __ldg(&wr[j]);
    }

    float c = 0.f;
    if (tid < HID) sh[tid] = 0.f;
    __syncthreads();

    for (int t = 0; t < NGRAPH; t++) {
        float a0 = g_gatesX[t * 512 + tid], a1 = 0.f, a2 = 0.f, a3 = 0.f;
#pragma unroll
        for (int j = 0; j < 16; j++) {
            float2 p0 = __half22float2(*(const __half2*)&wreg[j].x);
            float2 p1 = __half22float2(*(const __half2*)&wreg[j].y);
            float2 p2 = __half22float2(*(const __half2*)&wreg[j].z);
            float2 p3 = __half22float2(*(const __half2*)&wreg[j].w);
            const float* h = &sh[j * 8];
            a0 = fmaf(p0.x, h[0], a0); a1 = fmaf(p0.y, h[1], a1);
            a2 = fmaf(p1.x, h[2], a2); a3 = fmaf(p1.y, h[3], a3);
            a0 = fmaf(p2.x, h[4], a0); a1 = fmaf(p2.y, h[5], a1);
            a2 = fmaf(p3.x, h[6], a2); a3 = fmaf(p3.y, h[7], a3);
        }
        sg[tid] = (a0 + a1) + (a2 + a3);
        __syncthreads();
        if (tid < HID) {
            float iv = 1.f / (1.f + __expf(-sg[tid]));
            float fv = 1.f / (1.f + __expf(-sg[HID + tid]));
            float gv = tanhf(sg[2 * HID + tid]);
            float ov = 1.f / (1.f + __expf(-sg[3 * HID + tid]));
            c = fv * c + iv * gv;
            sh[tid] = ov * tanhf(c);
        }
        __syncthreads();
        if (tid < 320) {
            int k = tid >> 5, lane = tid & 31;
            const float4* wf = (const float4*)(W_fc + (size_t)k * HID);
            float4 w = __ldg(&wf[lane]);
            float4 h4 = *(const float4*)&sh[lane * 4];
            float p = w.x * h4.x + w.y * h4.y + w.z * h4.z + w.w * h4.w;
            for (int o = 16; o > 0; o >>= 1) p += __shfl_down_sync(0xffffffffu, p, o);
            if (lane == 0) out[t * 10 + k] = p + __ldg(&b_fc[k]);
        }
    }
}

// ---------------- launch ----------------
extern "C" void kernel_launch(void* const* d_in, const int* in_sizes, int n_in,
                              void* d_out, int out_size) {
    const float* x      = (const float*)d_in[0];
    const int*   ei     = (const int*)d_in[1];
    const int*   batch  = (const int*)d_in[2];
    const float* W_gcn  = (const float*)d_in[3];
    const float* b_gcn  = (const float*)d_in[4];
    const float* w_ih   = (const float*)d_in[5];
    const float* w_hh   = (const float*)d_in[6];
    const float* b_ih   = (const float*)d_in[7];
    const float* b_hh   = (const float*)d_in[8];
    const float* W_fc   = (const float*)d_in[9];
    const float* b_fc   = (const float*)d_in[10];
    float* out = (float*)d_out;

    int N = in_sizes[2];       // 100000 nodes
    int E = in_sizes[1] / 2;   // 1600000 edges
    int NB = (N + SCAN_BLK - 1) / SCAN_BLK;

    static cudaStream_t s2 = nullptr;
    static cudaEvent_t ev0 = nullptr, evS1 = nullptr, evB = nullptr;
    if (s2 == nullptr) {
        cudaStreamCreate(&s2);
        cudaEventCreateWithFlags(&ev0, cudaEventDisableTiming);
        cudaEventCreateWithFlags(&evS1, cudaEventDisableTiming);
        cudaEventCreateWithFlags(&evB, cudaEventDisableTiming);
    }

    cudaEventRecord(ev0, 0);
    cudaStreamWaitEvent(s2, ev0, 0);

    k_deg<<<(E + 255) / 256, 256>>>(ei, E);                                 // 1 (main)
    k_cvtx<<<(N * HID / 8 + 255) / 256, 256, 0, s2>>>(x, N * HID / 8);      // 2 (s2)
    k_cvtw<<<(4 * HID * HID + 255) / 256, 256, 0, s2>>>(W_gcn, w_hh);       // 3 (s2)
    k_scan1<<<NB, SCAN_BLK>>>(N);                                           // 4 (main) <- ncu
    k_gemm_tc<<<(N + 127) / 128, 256, 0, s2>>>(N);                          // 5 (s2)

    cudaEventRecord(evS1, 0);
    cudaStreamWaitEvent(s2, evS1, 0);
    k_yscale<<<(N * 16 + 255) / 256, 256, 0, s2>>>(N * 16);                 // 6 (s2)
    cudaEventRecord(evB, s2);

    k_scan23<<<NB, SCAN_BLK>>>(N, NB);                                      // 7 (main)
    k_fill<<<(E / 4 + 255) / 256, 256>>>(ei, E);                            // 8 (main)

    cudaStreamWaitEvent(0, evB, 0);
    k_agg<<<(N + 31) / 32, 256>>>(batch, b_gcn, N);                         // 9
    k_agg<<<(N + 31) / 32, 256>>>(batch, b_gcn, N);                         // 10 (probe: mean-preserving)
    k_gatesx<<<NGRAPH, 512>>>(w_ih, b_ih, b_hh, N);                         // 11
    k_lstm<<<1, 512>>>(W_fc, b_fc, out);                                    // 12
}

// round 16
// speedup vs baseline: 2.9295x; 1.2140x over previous
#include <cuda_runtime.h>
#include <cuda_fp16.h>
#include <math.h>

#define NMAX 100000
#define EMAX 1600000
#define HID 128
#define NGRAPH 64
#define SCAN_BLK 512

// ---------------- device scratch ----------------
__device__ __half g_xh[(size_t)NMAX * HID];
__device__ __half g_wt[HID * HID];
__device__ __half g_yh[(size_t)NMAX * HID];    // fp16 xt, scaled by dinv in k_yscale
__device__ float g_dinv[NMAX];
__device__ int   g_deg[NMAX];                  // zeroed by k_gatesx of PREVIOUS run (.bss on first)
__device__ int   g_start[NMAX + 1];
__device__ int   g_cursor[NMAX];
__device__ int   g_csr_src[EMAX];
__device__ int   g_part[(NMAX + SCAN_BLK - 1) / SCAN_BLK];
__device__ float g_gsum[NGRAPH * HID];         // zeroed by k_gatesx after read
__device__ float g_gcnt[NGRAPH];
__device__ float g_gatesX[NGRAPH * 4 * HID];
__device__ __half g_whh_h[4 * HID * HID];

// ---------------- fp16 conversions ----------------
__global__ void k_cvtx(const float* __restrict__ x, int total8) {
    int i = blockIdx.x * blockDim.x + threadIdx.x;
    if (i < total8) {
        float4 v0 = __ldg((const float4*)x + (size_t)i * 2);
        float4 v1 = __ldg((const float4*)x + (size_t)i * 2 + 1);
        __half2 h0 = __floats2half2_rn(v0.x, v0.y);
        __half2 h1 = __floats2half2_rn(v0.z, v0.w);
        __half2 h2 = __floats2half2_rn(v1.x, v1.y);
        __half2 h3 = __floats2half2_rn(v1.z, v1.w);
        uint4 p;
        p.x = *(unsigned*)&h0; p.y = *(unsigned*)&h1;
        p.z = *(unsigned*)&h2; p.w = *(unsigned*)&h3;
        *(uint4*)(g_xh + (size_t)i * 8) = p;
    }
}

__global__ void k_cvtw(const float* __restrict__ W, const float* __restrict__ w_hh) {
    int i = blockIdx.x * blockDim.x + threadIdx.x;
    if (i < HID * HID) {
        int n = i >> 7, k = i & 127;
        g_wt[n * HID + k] = __float2half(__ldg(&W[k * HID + n]));
    }
    if (i < 4 * HID * HID) g_whh_h[i] = __float2half(__ldg(&w_hh[i]));
}

// ---------------- degree histogram over col ----------------
__global__ void k_deg(const int* __restrict__ ei, int E) {
    int e = blockIdx.x * blockDim.x + threadIdx.x;
    if (e < E) atomicAdd(&g_deg[__ldg(&ei[(size_t)E + e])], 1);
}

// ---------------- scan pass 1: block sums + dinv ----------------
__global__ __launch_bounds__(SCAN_BLK) void k_scan1(int N) {
    int i = blockIdx.x * SCAN_BLK + threadIdx.x;
    int v = (i < N) ? g_deg[i] : 0;
    if (i < N) g_dinv[i] = rsqrtf((float)v + 1.0f);
    int s = v;
    for (int o = 16; o > 0; o >>= 1) s += __shfl_down_sync(0xffffffffu, s, o);
    __shared__ int ws[16];
    int wid = threadIdx.x >> 5, lane = threadIdx.x & 31;
    if (lane == 0) ws[wid] = s;
    __syncthreads();
    if (threadIdx.x < 16) {
        int t = ws[threadIdx.x];
        for (int o = 8; o > 0; o >>= 1) t += __shfl_down_sync(0xffffu, t, o);
        if (threadIdx.x == 0) g_part[blockIdx.x] = t;
    }
}

// ---------------- scan 2+3 merged ----------------
__global__ __launch_bounds__(SCAN_BLK) void k_scan23(int N, int NB) {
    int bid = blockIdx.x;
    int i = bid * SCAN_BLK + threadIdx.x;
    int v = (i < N) ? g_deg[i] : 0;
    int lane = threadIdx.x & 31, wid = threadIdx.x >> 5;
    int x = v;
    for (int o = 1; o < 32; o <<= 1) {
        int t = __shfl_up_sync(0xffffffffu, x, o);
        if (lane >= o) x += t;
    }
    __shared__ int ws[16], pws[16], sbase;
    if (lane == 31) ws[wid] = x;
    int pv = ((int)threadIdx.x < bid) ? g_part[threadIdx.x] : 0;
    for (int o = 16; o > 0; o >>= 1) pv += __shfl_down_sync(0xffffffffu, pv, o);
    if (lane == 0) pws[wid] = pv;
    __syncthreads();
    if (wid == 0 && lane < 16) {
        int t = ws[lane];
        for (int o = 1; o < 16; o <<= 1) {
            int u = __shfl_up_sync(0xffffu, t, o);
            if (lane >= o) t += u;
        }
        ws[lane] = t;
    }
    if (wid == 1 && lane < 16) {
        int t = pws[lane];
        for (int o = 8; o > 0; o >>= 1) t += __shfl_down_sync(0xffffu, t, o);
        if (lane == 0) sbase = t;
    }
    __syncthreads();
    int base = sbase + (wid > 0 ? ws[wid - 1] : 0);
    int excl = base + (x - v);
    if (i < N) { g_start[i] = excl; g_cursor[i] = excl; }
    if (i == N - 1) g_start[N] = excl + v;
}

// ---------------- CSR fill: 4 edges/thread, int4 loads ----------------
__global__ void k_fill(const int* __restrict__ ei, int E) {
    int q = blockIdx.x * blockDim.x + threadIdx.x;
    if (q * 4 < E) {
        int4 rows = __ldg((const int4*)(ei) + q);
        int4 cols = __ldg((const int4*)(ei + E) + q);
        int s0 = atomicAdd(&g_cursor[cols.x], 1); g_csr_src[s0] = rows.x;
        int s1 = atomicAdd(&g_cursor[cols.y], 1); g_csr_src[s1] = rows.y;
        int s2 = atomicAdd(&g_cursor[cols.z], 1); g_csr_src[s2] = rows.z;
        int s3 = atomicAdd(&g_cursor[cols.w], 1); g_csr_src[s3] = rows.w;
    }
}

// ---------------- tensor-core GEMM: yh[n] = fp16( x[n] @ W ) ----------------
__global__ __launch_bounds__(256) void k_gemm_tc(int M) {
    __shared__ __half xs[128][72];
    __shared__ __half ws[128][72];
    int tid = threadIdx.x;
    int warp = tid >> 5, lane = tid & 31;
    int wm = (warp & 3) * 32;
    int wn = (warp >> 2) * 64;
    int g = lane >> 2, tig = lane & 3;
    int m0 = blockIdx.x * 128;

    float acc[2][8][4];
#pragma unroll
    for (int mt = 0; mt < 2; mt++)
#pragma unroll
        for (int nt = 0; nt < 8; nt++)
#pragma unroll
            for (int q = 0; q < 4; q++) acc[mt][nt][q] = 0.f;

    for (int kc = 0; kc < 2; kc++) {
#pragma unroll
        for (int i = 0; i < 4; i++) {
            int idx = i * 256 + tid;
            int r = idx >> 3, q = idx & 7;
            int grow = m0 + r;
            uint4 v = make_uint4(0u, 0u, 0u, 0u);
            if (grow < M)
                v = *(const uint4*)(g_xh + (size_t)grow * HID + kc * 64 + q * 8);
            *(uint4*)(&xs[r][q * 8]) = v;
            uint4 w = *(const uint4*)(g_wt + r * HID + kc * 64 + q * 8);
            *(uint4*)(&ws[r][q * 8]) = w;
        }
        __syncthreads();
#pragma unroll
        for (int ks = 0; ks < 4; ks++) {
            int k0 = ks * 16;
            unsigned a[2][4];
#pragma unroll
            for (int mt = 0; mt < 2; mt++) {
                int row = wm + mt * 16 + g;
                a[mt][0] = *(const unsigned*)(&xs[row][k0 + tig * 2]);
                a[mt][1] = *(const unsigned*)(&xs[row + 8][k0 + tig * 2]);
                a[mt][2] = *(const unsigned*)(&xs[row][k0 + tig * 2 + 8]);
                a[mt][3] = *(const unsigned*)(&xs[row + 8][k0 + tig * 2 + 8]);
            }
#pragma unroll
            for (int nt = 0; nt < 8; nt++) {
                int n = wn + nt * 8 + g;
                unsigned b0 = *(const unsigned*)(&ws[n][k0 + tig * 2]);
                unsigned b1 = *(const unsigned*)(&ws[n][k0 + tig * 2 + 8]);
#pragma unroll
                for (int mt = 0; mt < 2; mt++) {
                    float* c = acc[mt][nt];
                    asm volatile(
                        "mma.sync.aligned.m16n8k16.row.col.f32.f16.f16.f32 "
                        "{%0,%1,%2,%3}, {%4,%5,%6,%7}, {%8,%9}, {%0,%1,%2,%3};"
                        : "+f"(c[0]), "+f"(c[1]), "+f"(c[2]), "+f"(c[3])
                        : "r"(a[mt][0]), "r"(a[mt][1]), "r"(a[mt][2]), "r"(a[mt][3]),
                          "r"(b0), "r"(b1));
                }
            }
        }
        __syncthreads();
    }

#pragma unroll
    for (int mt = 0; mt < 2; mt++) {
        int row = m0 + wm + mt * 16 + g;
#pragma unroll
        for (int nt = 0; nt < 8; nt++) {
            int col = wn + nt * 8 + tig * 2;
            float* c = acc[mt][nt];
            if (row < M) {
                __half2 h = __floats2half2_rn(c[0], c[1]);
                *(__half2*)(g_yh + (size_t)row * HID + col) = h;
            }
            if (row + 8 < M) {
                __half2 h = __floats2half2_rn(c[2], c[3]);
                *(__half2*)(g_yh + (size_t)(row + 8) * HID + col) = h;
            }
        }
    }
}

// ---------------- yscale: g_yh[n] *= dinv[n] ----------------
__global__ void k_yscale(int total16) {
    int i = blockIdx.x * blockDim.x + threadIdx.x;
    if (i < total16) {
        int n = i >> 4;
        uint4 v = *(const uint4*)(g_yh + (size_t)i * 8);
        __half2 dh = __float2half2_rn(g_dinv[n]);
        __half2* p = (__half2*)&v;
        p[0] = __hmul2(p[0], dh);
        p[1] = __hmul2(p[1], dh);
        p[2] = __hmul2(p[2], dh);
        p[3] = __hmul2(p[3], dh);
        *(uint4*)(g_yh + (size_t)i * 8) = v;
    }
}

// ---------------- fused gather-aggregate + relu + mean-pool ----------------
__device__ __forceinline__ void pool_flush(int g, float4 run, float crun, int lane) {
    float* dst = g_gsum + g * HID + lane * 4;
    asm volatile("red.global.add.v4.f32 [%0], {%1,%2,%3,%4};"
                 :: "l"(dst), "f"(run.x), "f"(run.y), "f"(run.z), "f"(run.w) : "memory");
    if (lane == 0) atomicAdd(&g_gcnt[g], crun);
}

__device__ __forceinline__ void add_row(float4& acc, uint2 r) {
    float2 lo = __half22float2(*(const __half2*)&r.x);
    float2 hi = __half22float2(*(const __half2*)&r.y);
    acc.x += lo.x; acc.y += lo.y; acc.z += hi.x; acc.w += hi.y;
}

__global__ __launch_bounds__(256) void k_agg(const int* __restrict__ batch,
                                             const float* __restrict__ b_gcn, int N) {
    int lane = threadIdx.x & 31, wid = threadIdx.x >> 5;
    int s0 = blockIdx.x * 32;
    int e0 = min(s0 + 32, N);
    int n0 = s0 + wid;
    if (n0 >= e0) return;

    float4 bb = __ldg((const float4*)(b_gcn + lane * 4));
    int curg = __ldg(&batch[n0]);
    float4 run = make_float4(0.f, 0.f, 0.f, 0.f);
    float crun = 0.f;

    for (int n = n0; n < e0; n += 8) {
        int gg = __ldg(&batch[n]);
        if (gg != curg) {
            pool_flush(curg, run, crun, lane);
            run = make_float4(0.f, 0.f, 0.f, 0.f);
            crun = 0.f;
            curg = gg;
        }
        int st = __ldg(&g_start[n]);
        int en = __ldg(&g_start[n + 1]);
        float dvn = __ldg(&g_dinv[n]);
        float4 acc = make_float4(0.f, 0.f, 0.f, 0.f);
        add_row(acc, __ldg((const uint2*)(g_yh + (size_t)n * HID) + lane));  // self loop
        for (int base = st; base < en; base += 32) {
            int cnt = min(32, en - base);
            int id = (lane < cnt) ? __ldg(&g_csr_src[base + lane]) : 0;
            int j = 0;
            for (; j + 4 <= cnt; j += 4) {
                int a0 = __shfl_sync(0xffffffffu, id, j);
                int a1 = __shfl_sync(0xffffffffu, id, j + 1);
                int a2 = __shfl_sync(0xffffffffu, id, j + 2);
                int a3 = __shfl_sync(0xffffffffu, id, j + 3);
                uint2 r0 = __ldg((const uint2*)(g_yh + (size_t)a0 * HID) + lane);
                uint2 r1 = __ldg((const uint2*)(g_yh + (size_t)a1 * HID) + lane);
                uint2 r2 = __ldg((const uint2*)(g_yh + (size_t)a2 * HID) + lane);
                uint2 r3 = __ldg((const uint2*)(g_yh + (size_t)a3 * HID) + lane);
                add_row(acc, r0);
                add_row(acc, r1);
                add_row(acc, r2);
                add_row(acc, r3);
            }
            for (; j < cnt; j++) {
                int a0 = __shfl_sync(0xffffffffu, id, j);
                add_row(acc, __ldg((const uint2*)(g_yh + (size_t)a0 * HID) + lane));
            }
        }
        run.x += fmaxf(fmaf(acc.x, dvn, bb.x), 0.f);
        run.y += fmaxf(fmaf(acc.y, dvn, bb.y), 0.f);
        run.z += fmaxf(fmaf(acc.z, dvn, bb.z), 0.f);
        run.w += fmaxf(fmaf(acc.w, dvn, bb.w), 0.f);
        crun += 1.f;
    }
    pool_flush(curg, run, crun, lane);
}

// ---------------- input-side LSTM gates + state re-zero for next replay ----------------
__global__ __launch_bounds__(512) void k_gatesx(const float* __restrict__ w_ih,
                                                const float* __restrict__ b_ih,
                                                const float* __restrict__ b_hh, int N) {
    __shared__ float p[HID];
    int t = blockIdx.x;
    if (threadIdx.x < HID) {
        float c = fmaxf(g_gcnt[t], 1.f);
        p[threadIdx.x] = g_gsum[t * HID + threadIdx.x] / c;
    }
    __syncthreads();
    int gg = threadIdx.x;
    const float4* wr = (const float4*)(w_ih + (size_t)gg * HID);
    float acc = __ldg(&b_ih[gg]) + __ldg(&b_hh[gg]);
#pragma unroll
    for (int j = 0; j < 32; j++) {
        float4 w = __ldg(wr + j);
        acc += w.x * p[j * 4] + w.y * p[j * 4 + 1] + w.z * p[j * 4 + 2] + w.w * p[j * 4 + 3];
    }
    g_gatesX[t * 512 + gg] = acc;
    // re-zero accumulators for the NEXT kernel_launch invocation (post-read)
    if (threadIdx.x < HID) g_gsum[t * HID + threadIdx.x] = 0.f;
    if (threadIdx.x == 0) g_gcnt[t] = 0.f;
    for (int i = t * 512 + threadIdx.x; i < N; i += NGRAPH * 512) g_deg[i] = 0;
}

// ---------------- recurrent LSTM: REGISTER-RESIDENT fp16 weights + fused FC ----------------
__global__ __launch_bounds__(512) void k_lstm(const float* __restrict__ W_fc,
                                              const float* __restrict__ b_fc,
                                              float* __restrict__ out) {
    __shared__ float sh[HID];
    __shared__ float sg[4 * HID];
    int tid = threadIdx.x;

    // one-time weight load: row tid of w_hh into registers (16 x uint4 = 64 regs)
    uint4 wreg[16];
    {
        const uint4* wr = (const uint4*)(g_whh_h + (size_t)tid * HID);
#pragma unroll
        for (int j = 0; j < 16; j++) wreg[j] = __ldg(&wr[j]);
    }

    float c = 0.f;
    if (tid < HID) sh[tid] = 0.f;
    __syncthreads();

    for (int t = 0; t < NGRAPH; t++) {
        float a0 = g_gatesX[t * 512 + tid], a1 = 0.f, a2 = 0.f, a3 = 0.f;
#pragma unroll
        for (int j = 0; j < 16; j++) {
            float2 p0 = __half22float2(*(const __half2*)&wreg[j].x);
            float2 p1 = __half22float2(*(const __half2*)&wreg[j].y);
            float2 p2 = __half22float2(*(const __half2*)&wreg[j].z);
            float2 p3 = __half22float2(*(const __half2*)&wreg[j].w);
            const float* h = &sh[j * 8];
            a0 = fmaf(p0.x, h[0], a0); a1 = fmaf(p0.y, h[1], a1);
            a2 = fmaf(p1.x, h[2], a2); a3 = fmaf(p1.y, h[3], a3);
            a0 = fmaf(p2.x, h[4], a0); a1 = fmaf(p2.y, h[5], a1);
            a2 = fmaf(p3.x, h[6], a2); a3 = fmaf(p3.y, h[7], a3);
        }
        sg[tid] = (a0 + a1) + (a2 + a3);
        __syncthreads();
        if (tid < HID) {
            float iv = 1.f / (1.f + __expf(-sg[tid]));
            float fv = 1.f / (1.f + __expf(-sg[HID + tid]));
            float gv = tanhf(sg[2 * HID + tid]);
            float ov = 1.f / (1.f + __expf(-sg[3 * HID + tid]));
            c = fv * c + iv * gv;
            sh[tid] = ov * tanhf(c);
        }
        __syncthreads();
        if (tid < 320) {
            int k = tid >> 5, lane = tid & 31;
            const float4* wf = (const float4*)(W_fc + (size_t)k * HID);
            float4 w = __ldg(&wf[lane]);
            float4 h4 = *(const float4*)&sh[lane * 4];
            float p = w.x * h4.x + w.y * h4.y + w.z * h4.z + w.w * h4.w;
            for (int o = 16; o > 0; o >>= 1) p += __shfl_down_sync(0xffffffffu, p, o);
            if (lane == 0) out[t * 10 + k] = p + __ldg(&b_fc[k]);
        }
    }
}

// ---------------- launch ----------------
extern "C" void kernel_launch(void* const* d_in, const int* in_sizes, int n_in,
                              void* d_out, int out_size) {
    const float* x      = (const float*)d_in[0];
    const int*   ei     = (const int*)d_in[1];
    const int*   batch  = (const int*)d_in[2];
    const float* W_gcn  = (const float*)d_in[3];
    const float* b_gcn  = (const float*)d_in[4];
    const float* w_ih   = (const float*)d_in[5];
    const float* w_hh   = (const float*)d_in[6];
    const float* b_ih   = (const float*)d_in[7];
    const float* b_hh   = (const float*)d_in[8];
    const float* W_fc   = (const float*)d_in[9];
    const float* b_fc   = (const float*)d_in[10];
    float* out = (float*)d_out;

    int N = in_sizes[2];       // 100000 nodes
    int E = in_sizes[1] / 2;   // 1600000 edges
    int NB = (N + SCAN_BLK - 1) / SCAN_BLK;

    static cudaStream_t s2 = nullptr;
    static cudaEvent_t ev0 = nullptr, evS1 = nullptr, evB = nullptr;
    if (s2 == nullptr) {
        cudaStreamCreate(&s2);
        cudaEventCreateWithFlags(&ev0, cudaEventDisableTiming);
        cudaEventCreateWithFlags(&evS1, cudaEventDisableTiming);
        cudaEventCreateWithFlags(&evB, cudaEventDisableTiming);
    }

    cudaEventRecord(ev0, 0);
    cudaStreamWaitEvent(s2, ev0, 0);

    k_deg<<<(E + 255) / 256, 256>>>(ei, E);                                 // 1 (main)
    k_cvtx<<<(N * HID / 8 + 255) / 256, 256, 0, s2>>>(x, N * HID / 8);      // 2 (s2)
    k_cvtw<<<(4 * HID * HID + 255) / 256, 256, 0, s2>>>(W_gcn, w_hh);       // 3 (s2)
    k_scan1<<<NB, SCAN_BLK>>>(N);                                           // 4 (main) <- ncu
    k_gemm_tc<<<(N + 127) / 128, 256, 0, s2>>>(N);                          // 5 (s2)

    cudaEventRecord(evS1, 0);
    cudaStreamWaitEvent(s2, evS1, 0);
    k_yscale<<<(N * 16 + 255) / 256, 256, 0, s2>>>(N * 16);                 // 6 (s2)
    cudaEventRecord(evB, s2);

    k_scan23<<<NB, SCAN_BLK>>>(N, NB);                                      // 7 (main)
    k_fill<<<(E / 4 + 255) / 256, 256>>>(ei, E);                            // 8 (main)

    cudaStreamWaitEvent(0, evB, 0);
    k_agg<<<(N + 31) / 32, 256>>>(batch, b_gcn, N);                         // 9 (probe removed)
    k_gatesx<<<NGRAPH, 512>>>(w_ih, b_ih, b_hh, N);                         // 10
    k_lstm<<<1, 512>>>(W_fc, b_fc, out);                                    // 11
}

// round 17
// speedup vs baseline: 2.9948x; 1.0223x over previous
#include <cuda_runtime.h>
#include <cuda_fp16.h>
#include <math.h>

#define NMAX 100000
#define EMAX 1600000
#define HID 128
#define NGRAPH 64
#define SCAN_BLK 512

// ---------------- device scratch ----------------
__device__ __half g_xh[(size_t)NMAX * HID];
__device__ __half g_wt[HID * HID];
__device__ __half g_yh[(size_t)NMAX * HID];    // fp16 xt, scaled by dinv in k_yscale
__device__ float g_dinv[NMAX];
__device__ int   g_deg[NMAX];                  // zeroed by k_gatesx of PREVIOUS run (.bss on first)
__device__ int   g_start[NMAX + 1];
__device__ int   g_cursor[NMAX];
__device__ int   g_csr_src[EMAX];
__device__ int   g_part[(NMAX + SCAN_BLK - 1) / SCAN_BLK];
__device__ float g_gsum[NGRAPH * HID];         // zeroed by k_gatesx after read
__device__ float g_gcnt[NGRAPH];
__device__ float g_gatesX[NGRAPH * 4 * HID];
__device__ __half g_whh_h[4 * HID * HID];

// ---------------- fast activations ----------------
__device__ __forceinline__ float fast_tanh(float x) {
    float y;
    asm("tanh.approx.f32 %0, %1;" : "=f"(y) : "f"(x));
    return y;
}
__device__ __forceinline__ float fast_sigmoid(float x) {
    float e;
    asm("ex2.approx.f32 %0, %1;" : "=f"(e) : "f"(-x * 1.4426950408889634f));
    float r;
    asm("rcp.approx.f32 %0, %1;" : "=f"(r) : "f"(1.0f + e));
    return r;
}

// ---------------- fp16 conversions ----------------
__global__ void k_cvtx(const float* __restrict__ x, int total8) {
    int i = blockIdx.x * blockDim.x + threadIdx.x;
    if (i < total8) {
        float4 v0 = __ldg((const float4*)x + (size_t)i * 2);
        float4 v1 = __ldg((const float4*)x + (size_t)i * 2 + 1);
        __half2 h0 = __floats2half2_rn(v0.x, v0.y);
        __half2 h1 = __floats2half2_rn(v0.z, v0.w);
        __half2 h2 = __floats2half2_rn(v1.x, v1.y);
        __half2 h3 = __floats2half2_rn(v1.z, v1.w);
        uint4 p;
        p.x = *(unsigned*)&h0; p.y = *(unsigned*)&h1;
        p.z = *(unsigned*)&h2; p.w = *(unsigned*)&h3;
        *(uint4*)(g_xh + (size_t)i * 8) = p;
    }
}

__global__ void k_cvtw(const float* __restrict__ W, const float* __restrict__ w_hh) {
    int i = blockIdx.x * blockDim.x + threadIdx.x;
    if (i < HID * HID) {
        int n = i >> 7, k = i & 127;
        g_wt[n * HID + k] = __float2half(__ldg(&W[k * HID + n]));
    }
    if (i < 4 * HID * HID) g_whh_h[i] = __float2half(__ldg(&w_hh[i]));
}

// ---------------- degree histogram over col ----------------
__global__ void k_deg(const int* __restrict__ ei, int E) {
    int e = blockIdx.x * blockDim.x + threadIdx.x;
    if (e < E) atomicAdd(&g_deg[__ldg(&ei[(size_t)E + e])], 1);
}

// ---------------- scan pass 1: block sums + dinv ----------------
__global__ __launch_bounds__(SCAN_BLK) void k_scan1(int N) {
    int i = blockIdx.x * SCAN_BLK + threadIdx.x;
    int v = (i < N) ? g_deg[i] : 0;
    if (i < N) g_dinv[i] = rsqrtf((float)v + 1.0f);
    int s = v;
    for (int o = 16; o > 0; o >>= 1) s += __shfl_down_sync(0xffffffffu, s, o);
    __shared__ int ws[16];
    int wid = threadIdx.x >> 5, lane = threadIdx.x & 31;
    if (lane == 0) ws[wid] = s;
    __syncthreads();
    if (threadIdx.x < 16) {
        int t = ws[threadIdx.x];
        for (int o = 8; o > 0; o >>= 1) t += __shfl_down_sync(0xffffu, t, o);
        if (threadIdx.x == 0) g_part[blockIdx.x] = t;
    }
}

// ---------------- scan 2+3 merged ----------------
__global__ __launch_bounds__(SCAN_BLK) void k_scan23(int N, int NB) {
    int bid = blockIdx.x;
    int i = bid * SCAN_BLK + threadIdx.x;
    int v = (i < N) ? g_deg[i] : 0;
    int lane = threadIdx.x & 31, wid = threadIdx.x >> 5;
    int x = v;
    for (int o = 1; o < 32; o <<= 1) {
        int t = __shfl_up_sync(0xffffffffu, x, o);
        if (lane >= o) x += t;
    }
    __shared__ int ws[16], pws[16], sbase;
    if (lane == 31) ws[wid] = x;
    int pv = ((int)threadIdx.x < bid) ? g_part[threadIdx.x] : 0;
    for (int o = 16; o > 0; o >>= 1) pv += __shfl_down_sync(0xffffffffu, pv, o);
    if (lane == 0) pws[wid] = pv;
    __syncthreads();
    if (wid == 0 && lane < 16) {
        int t = ws[lane];
        for (int o = 1; o < 16; o <<= 1) {
            int u = __shfl_up_sync(0xffffu, t, o);
            if (lane >= o) t += u;
        }
        ws[lane] = t;
    }
    if (wid == 1 && lane < 16) {
        int t = pws[lane];
        for (int o = 8; o > 0; o >>= 1) t += __shfl_down_sync(0xffffu, t, o);
        if (lane == 0) sbase = t;
    }
    __syncthreads();
    int base = sbase + (wid > 0 ? ws[wid - 1] : 0);
    int excl = base + (x - v);
    if (i < N) { g_start[i] = excl; g_cursor[i] = excl; }
    if (i == N - 1) g_start[N] = excl + v;
}

// ---------------- CSR fill: 4 edges/thread, int4 loads ----------------
__global__ void k_fill(const int* __restrict__ ei, int E) {
    int q = blockIdx.x * blockDim.x + threadIdx.x;
    if (q * 4 < E) {
        int4 rows = __ldg((const int4*)(ei) + q);
        int4 cols = __ldg((const int4*)(ei + E) + q);
        int s0 = atomicAdd(&g_cursor[cols.x], 1); g_csr_src[s0] = rows.x;
        int s1 = atomicAdd(&g_cursor[cols.y], 1); g_csr_src[s1] = rows.y;
        int s2 = atomicAdd(&g_cursor[cols.z], 1); g_csr_src[s2] = rows.z;
        int s3 = atomicAdd(&g_cursor[cols.w], 1); g_csr_src[s3] = rows.w;
    }
}

// ---------------- tensor-core GEMM: yh[n] = fp16( x[n] @ W ) ----------------
__global__ __launch_bounds__(256) void k_gemm_tc(int M) {
    __shared__ __half xs[128][72];
    __shared__ __half ws[128][72];
    int tid = threadIdx.x;
    int warp = tid >> 5, lane = tid & 31;
    int wm = (warp & 3) * 32;
    int wn = (warp >> 2) * 64;
    int g = lane >> 2, tig = lane & 3;
    int m0 = blockIdx.x * 128;

    float acc[2][8][4];
#pragma unroll
    for (int mt = 0; mt < 2; mt++)
#pragma unroll
        for (int nt = 0; nt < 8; nt++)
#pragma unroll
            for (int q = 0; q < 4; q++) acc[mt][nt][q] = 0.f;

    for (int kc = 0; kc < 2; kc++) {
#pragma unroll
        for (int i = 0; i < 4; i++) {
            int idx = i * 256 + tid;
            int r = idx >> 3, q = idx & 7;
            int grow = m0 + r;
            uint4 v = make_uint4(0u, 0u, 0u, 0u);
            if (grow < M)
                v = *(const uint4*)(g_xh + (size_t)grow * HID + kc * 64 + q * 8);
            *(uint4*)(&xs[r][q * 8]) = v;
            uint4 w = *(const uint4*)(g_wt + r * HID + kc * 64 + q * 8);
            *(uint4*)(&ws[r][q * 8]) = w;
        }
        __syncthreads();
#pragma unroll
        for (int ks = 0; ks < 4; ks++) {
            int k0 = ks * 16;
            unsigned a[2][4];
#pragma unroll
            for (int mt = 0; mt < 2; mt++) {
                int row = wm + mt * 16 + g;
                a[mt][0] = *(const unsigned*)(&xs[row][k0 + tig * 2]);
                a[mt][1] = *(const unsigned*)(&xs[row + 8][k0 + tig * 2]);
                a[mt][2] = *(const unsigned*)(&xs[row][k0 + tig * 2 + 8]);
                a[mt][3] = *(const unsigned*)(&xs[row + 8][k0 + tig * 2 + 8]);
            }
#pragma unroll
            for (int nt = 0; nt < 8; nt++) {
                int n = wn + nt * 8 + g;
                unsigned b0 = *(const unsigned*)(&ws[n][k0 + tig * 2]);
                unsigned b1 = *(const unsigned*)(&ws[n][k0 + tig * 2 + 8]);
#pragma unroll
                for (int mt = 0; mt < 2; mt++) {
                    float* c = acc[mt][nt];
                    asm volatile(
                        "mma.sync.aligned.m16n8k16.row.col.f32.f16.f16.f32 "
                        "{%0,%1,%2,%3}, {%4,%5,%6,%7}, {%8,%9}, {%0,%1,%2,%3};"
                        : "+f"(c[0]), "+f"(c[1]), "+f"(c[2]), "+f"(c[3])
                        : "r"(a[mt][0]), "r"(a[mt][1]), "r"(a[mt][2]), "r"(a[mt][3]),
                          "r"(b0), "r"(b1));
                }
            }
        }
        __syncthreads();
    }

#pragma unroll
    for (int mt = 0; mt < 2; mt++) {
        int row = m0 + wm + mt * 16 + g;
#pragma unroll
        for (int nt = 0; nt < 8; nt++) {
            int col = wn + nt * 8 + tig * 2;
            float* c = acc[mt][nt];
            if (row < M) {
                __half2 h = __floats2half2_rn(c[0], c[1]);
                *(__half2*)(g_yh + (size_t)row * HID + col) = h;
            }
            if (row + 8 < M) {
                __half2 h = __floats2half2_rn(c[2], c[3]);
                *(__half2*)(g_yh + (size_t)(row + 8) * HID + col) = h;
            }
        }
    }
}

// ---------------- yscale: g_yh[n] *= dinv[n] ----------------
__global__ void k_yscale(int total16) {
    int i = blockIdx.x * blockDim.x + threadIdx.x;
    if (i < total16) {
        int n = i >> 4;
        uint4 v = *(const uint4*)(g_yh + (size_t)i * 8);
        __half2 dh = __float2half2_rn(g_dinv[n]);
        __half2* p = (__half2*)&v;
        p[0] = __hmul2(p[0], dh);
        p[1] = __hmul2(p[1], dh);
        p[2] = __hmul2(p[2], dh);
        p[3] = __hmul2(p[3], dh);
        *(uint4*)(g_yh + (size_t)i * 8) = v;
    }
}

// ---------------- fused gather-aggregate + relu + mean-pool ----------------
__device__ __forceinline__ void pool_flush(int g, float4 run, float crun, int lane) {
    float* dst = g_gsum + g * HID + lane * 4;
    asm volatile("red.global.add.v4.f32 [%0], {%1,%2,%3,%4};"
                 :: "l"(dst), "f"(run.x), "f"(run.y), "f"(run.z), "f"(run.w) : "memory");
    if (lane == 0) atomicAdd(&g_gcnt[g], crun);
}

__device__ __forceinline__ void add_row(float4& acc, uint2 r) {
    float2 lo = __half22float2(*(const __half2*)&r.x);
    float2 hi = __half22float2(*(const __half2*)&r.y);
    acc.x += lo.x; acc.y += lo.y; acc.z += hi.x; acc.w += hi.y;
}

__global__ __launch_bounds__(256) void k_agg(const int* __restrict__ batch,
                                             const float* __restrict__ b_gcn, int N) {
    int lane = threadIdx.x & 31, wid = threadIdx.x >> 5;
    int s0 = blockIdx.x * 32;
    int e0 = min(s0 + 32, N);
    int n0 = s0 + wid;
    if (n0 >= e0) return;

    float4 bb = __ldg((const float4*)(b_gcn + lane * 4));
    int curg = __ldg(&batch[n0]);
    float4 run = make_float4(0.f, 0.f, 0.f, 0.f);
    float crun = 0.f;

    for (int n = n0; n < e0; n += 8) {
        int gg = __ldg(&batch[n]);
        if (gg != curg) {
            pool_flush(curg, run, crun, lane);
            run = make_float4(0.f, 0.f, 0.f, 0.f);
            crun = 0.f;
            curg = gg;
        }
        int st = __ldg(&g_start[n]);
        int en = __ldg(&g_start[n + 1]);
        float dvn = __ldg(&g_dinv[n]);
        float4 acc = make_float4(0.f, 0.f, 0.f, 0.f);
        add_row(acc, __ldg((const uint2*)(g_yh + (size_t)n * HID) + lane));  // self loop
        for (int base = st; base < en; base += 32) {
            int cnt = min(32, en - base);
            int id = (lane < cnt) ? __ldg(&g_csr_src[base + lane]) : 0;
            int j = 0;
            for (; j + 4 <= cnt; j += 4) {
                int a0 = __shfl_sync(0xffffffffu, id, j);
                int a1 = __shfl_sync(0xffffffffu, id, j + 1);
                int a2 = __shfl_sync(0xffffffffu, id, j + 2);
                int a3 = __shfl_sync(0xffffffffu, id, j + 3);
                uint2 r0 = __ldg((const uint2*)(g_yh + (size_t)a0 * HID) + lane);
                uint2 r1 = __ldg((const uint2*)(g_yh + (size_t)a1 * HID) + lane);
                uint2 r2 = __ldg((const uint2*)(g_yh + (size_t)a2 * HID) + lane);
                uint2 r3 = __ldg((const uint2*)(g_yh + (size_t)a3 * HID) + lane);
                add_row(acc, r0);
                add_row(acc, r1);
                add_row(acc, r2);
                add_row(acc, r3);
            }
            for (; j < cnt; j++) {
                int a0 = __shfl_sync(0xffffffffu, id, j);
                add_row(acc, __ldg((const uint2*)(g_yh + (size_t)a0 * HID) + lane));
            }
        }
        run.x += fmaxf(fmaf(acc.x, dvn, bb.x), 0.f);
        run.y += fmaxf(fmaf(acc.y, dvn, bb.y), 0.f);
        run.z += fmaxf(fmaf(acc.z, dvn, bb.z), 0.f);
        run.w += fmaxf(fmaf(acc.w, dvn, bb.w), 0.f);
        crun += 1.f;
    }
    pool_flush(curg, run, crun, lane);
}

// ---------------- input-side LSTM gates + state re-zero for next replay ----------------
__global__ __launch_bounds__(512) void k_gatesx(const float* __restrict__ w_ih,
                                                const float* __restrict__ b_ih,
                                                const float* __restrict__ b_hh, int N) {
    __shared__ float p[HID];
    int t = blockIdx.x;
    if (threadIdx.x < HID) {
        float c = fmaxf(g_gcnt[t], 1.f);
        p[threadIdx.x] = g_gsum[t * HID + threadIdx.x] / c;
    }
    __syncthreads();
    int gg = threadIdx.x;
    const float4* wr = (const float4*)(w_ih + (size_t)gg * HID);
    float acc = __ldg(&b_ih[gg]) + __ldg(&b_hh[gg]);
#pragma unroll
    for (int j = 0; j < 32; j++) {
        float4 w = __ldg(wr + j);
        acc += w.x * p[j * 4] + w.y * p[j * 4 + 1] + w.z * p[j * 4 + 2] + w.w * p[j * 4 + 3];
    }
    g_gatesX[t * 512 + gg] = acc;
    // re-zero accumulators for the NEXT kernel_launch invocation (post-read)
    if (threadIdx.x < HID) g_gsum[t * HID + threadIdx.x] = 0.f;
    if (threadIdx.x == 0) g_gcnt[t] = 0.f;
    for (int i = t * 512 + threadIdx.x; i < N; i += NGRAPH * 512) g_deg[i] = 0;
}

// ---------------- recurrent LSTM: reg-resident weights, prefetched gatesX,
//                  HW-approx activations, deferred FC ----------------
__global__ __launch_bounds__(512) void k_lstm(const float* __restrict__ W_fc,
                                              const float* __restrict__ b_fc,
                                              float* __restrict__ out) {
    __shared__ float sh[HID];
    __shared__ float sg[4 * HID];
    __shared__ float shs[NGRAPH * HID];   // h history for deferred FC (32 KB)
    int tid = threadIdx.x;

    // one-time weight load: row tid of w_hh into registers (16 x uint4 = 64 regs)
    uint4 wreg[16];
    {
        const uint4* wr = (const uint4*)(g_whh_h + (size_t)tid * HID);
#pragma unroll
        for (int j = 0; j < 16; j++) wreg[j] = __ldg(&wr[j]);
    }

    float c = 0.f;
    if (tid < HID) sh[tid] = 0.f;
    float gx = __ldg(&g_gatesX[tid]);     // prefetch t=0
    __syncthreads();

    for (int t = 0; t < NGRAPH; t++) {
        // prefetch next step's gate input early (latency hidden under matvec)
        float gx_next = (t + 1 < NGRAPH) ? __ldg(&g_gatesX[(t + 1) * 512 + tid]) : 0.f;

        float a0 = gx, a1 = 0.f, a2 = 0.f, a3 = 0.f;
#pragma unroll
        for (int j = 0; j < 16; j++) {
            float2 p0 = __half22float2(*(const __half2*)&wreg[j].x);
            float2 p1 = __half22float2(*(const __half2*)&wreg[j].y);
            float2 p2 = __half22float2(*(const __half2*)&wreg[j].z);
            float2 p3 = __half22float2(*(const __half2*)&wreg[j].w);
            const float* h = &sh[j * 8];
            a0 = fmaf(p0.x, h[0], a0); a1 = fmaf(p0.y, h[1], a1);
            a2 = fmaf(p1.x, h[2], a2); a3 = fmaf(p1.y, h[3], a3);
            a0 = fmaf(p2.x, h[4], a0); a1 = fmaf(p2.y, h[5], a1);
            a2 = fmaf(p3.x, h[6], a2); a3 = fmaf(p3.y, h[7], a3);
        }
        sg[tid] = (a0 + a1) + (a2 + a3);
        __syncthreads();
        if (tid < HID) {
            float iv = fast_sigmoid(sg[tid]);
            float fv = fast_sigmoid(sg[HID + tid]);
            float gv = fast_tanh(sg[2 * HID + tid]);
            float ov = fast_sigmoid(sg[3 * HID + tid]);
            c = fv * c + iv * gv;
            float h = ov * fast_tanh(c);
            sh[tid] = h;
            shs[t * HID + tid] = h;
        }
        __syncthreads();
        gx = gx_next;
    }

    // deferred FC: 640 outputs across 512 threads
    for (int idx = tid; idx < NGRAPH * 10; idx += 512) {
        int t = idx / 10, k = idx % 10;
        const float4* wf = (const float4*)(W_fc + (size_t)k * HID);
        const float4* hv = (const float4*)&shs[t * HID];
        float acc = __ldg(&b_fc[k]);
#pragma unroll
        for (int j = 0; j < 32; j++) {
            float4 w = __ldg(&wf[j]);
            float4 h4 = hv[j];
            acc += w.x * h4.x + w.y * h4.y + w.z * h4.z + w.w * h4.w;
        }
        out[idx] = acc;
    }
}

// ---------------- launch ----------------
extern "C" void kernel_launch(void* const* d_in, const int* in_sizes, int n_in,
                              void* d_out, int out_size) {
    const float* x      = (const float*)d_in[0];
    const int*   ei     = (const int*)d_in[1];
    const int*   batch  = (const int*)d_in[2];
    const float* W_gcn  = (const float*)d_in[3];
    const float* b_gcn  = (const float*)d_in[4];
    const float* w_ih   = (const float*)d_in[5];
    const float* w_hh   = (const float*)d_in[6];
    const float* b_ih   = (const float*)d_in[7];
    const float* b_hh   = (const float*)d_in[8];
    const float* W_fc   = (const float*)d_in[9];
    const float* b_fc   = (const float*)d_in[10];
    float* out = (float*)d_out;

    int N = in_sizes[2];       // 100000 nodes
    int E = in_sizes[1] / 2;   // 1600000 edges
    int NB = (N + SCAN_BLK - 1) / SCAN_BLK;

    static cudaStream_t s2 = nullptr;
    static cudaEvent_t ev0 = nullptr, evS1 = nullptr, evB = nullptr;
    if (s2 == nullptr) {
        cudaStreamCreate(&s2);
        cudaEventCreateWithFlags(&ev0, cudaEventDisableTiming);
        cudaEventCreateWithFlags(&evS1, cudaEventDisableTiming);
        cudaEventCreateWithFlags(&evB, cudaEventDisableTiming);
    }

    cudaEventRecord(ev0, 0);
    cudaStreamWaitEvent(s2, ev0, 0);

    k_deg<<<(E + 255) / 256, 256>>>(ei, E);                                 // 1 (main)
    k_cvtx<<<(N * HID / 8 + 255) / 256, 256, 0, s2>>>(x, N * HID / 8);      // 2 (s2)
    k_cvtw<<<(4 * HID * HID + 255) / 256, 256, 0, s2>>>(W_gcn, w_hh);       // 3 (s2)
    k_scan1<<<NB, SCAN_BLK>>>(N);                                           // 4 (main) <- ncu
    k_gemm_tc<<<(N + 127) / 128, 256, 0, s2>>>(N);                          // 5 (s2)

    cudaEventRecord(evS1, 0);
    cudaStreamWaitEvent(s2, evS1, 0);
    k_yscale<<<(N * 16 + 255) / 256, 256, 0, s2>>>(N * 16);                 // 6 (s2)
    cudaEventRecord(evB, s2);

    k_scan23<<<NB, SCAN_BLK>>>(N, NB);                                      // 7 (main)
    k_fill<<<(E / 4 + 255) / 256, 256>>>(ei, E);                            // 8 (main)

    cudaStreamWaitEvent(0, evB, 0);
    k_agg<<<(N + 31) / 32, 256>>>(batch, b_gcn, N);                         // 9
    k_gatesx<<<NGRAPH, 512>>>(w_ih, b_ih, b_hh, N);                         // 10
    k_lstm<<<1, 512>>>(W_fc, b_fc, out);                                    // 11
}